// round 9
// baseline (speedup 1.0000x reference)
#include <cuda_runtime.h>

// Problem constants
#define Bn 2
#define Ln 16
#define Cn 16
#define Hn 64
#define Wn 64
#define HW (Hn * Wn)            // 4096

// Padded transposed image: entry = 16 channels (64B).
// Rows cover y = -1..65 (PR=67), cols cover x = -1..64 (PC=66).
// Border entries are never written -> stay zero (device globals zero-init).
#define PR 67
#define PC 66
#define PLANE (PR * PC)         // 4422 entries per (b,l)

__device__ float g_imgT[Bn * Ln * PLANE * Cn];   // ~9.06 MB
__device__ float g_cum[Bn * Ln * 2 * HW];        // cumsum of flows over L: 1 MB

#define N_TRANS (Bn * Ln * HW)        // 131072 transpose threads
#define N_CUM   (Bn * 2 * HW)         // 16384 cumsum threads

// ---------------------------------------------------------------------------
// Kernel 1 (fused prep):
//  threads [0, N_TRANS):  transpose images (B,L,C,H,W) -> padded (B,L,y,x,C)
//  threads [N_TRANS, +N_CUM): cumsum of flows over L (loads independent,
//  only the fp-add chain is serial)
// ---------------------------------------------------------------------------
__global__ void __launch_bounds__(256) prep_kernel(const float* __restrict__ images,
                                                   const float* __restrict__ flows) {
    int t = blockIdx.x * blockDim.x + threadIdx.x;
    if (t < N_TRANS) {
        int hw = t & (HW - 1);
        int bl = t >> 12;
        int w = hw & (Wn - 1);
        int h = hw >> 6;

        const float* src = images + (size_t)bl * Cn * HW + hw;
        float v[Cn];
#pragma unroll
        for (int c = 0; c < Cn; c++) v[c] = src[(size_t)c * HW];

        size_t e = (size_t)bl * PLANE + (size_t)(h + 1) * PC + (w + 1);
        float4* dst = reinterpret_cast<float4*>(g_imgT + e * Cn);
#pragma unroll
        for (int q = 0; q < 4; q++)
            dst[q] = make_float4(v[4 * q + 0], v[4 * q + 1], v[4 * q + 2], v[4 * q + 3]);
    } else if (t < N_TRANS + N_CUM) {
        int t2 = t - N_TRANS;
        int hw = t2 & (HW - 1);
        int d  = (t2 >> 12) & 1;
        int b  = t2 >> 13;

        float f[Ln];
        const float* fp = flows + ((size_t)(b * Ln) * 2 + d) * HW + hw;
#pragma unroll
        for (int l = 0; l < Ln; l++) f[l] = fp[(size_t)(l * 2) * HW];   // independent loads

        float acc = 0.0f;
        float* cp = g_cum + ((size_t)(b * Ln) * 2 + d) * HW + hw;
#pragma unroll
        for (int l = 0; l < Ln; l++) {
            acc += f[l];
            cp[(size_t)(l * 2) * HW] = acc;
        }
    }
}

// ---------------------------------------------------------------------------
// Kernel 2: main. 4 lanes per pixel, each lane owns a float4 of channels.
// Zero-padded image -> no masking/clamp logic. cum[j] loads are
// address-independent (no loop-carried load chain); unroll 4 for MLP.
// ---------------------------------------------------------------------------
__global__ void __launch_bounds__(256) gridsample_pscan_kernel(float* __restrict__ out) {
    int t = blockIdx.x * blockDim.x + threadIdx.x;   // 0 .. B*L*HW*4-1
    int cg = t & 3;              // channel group (4 channels)
    int pg = t >> 2;             // b*L*HW + hw
    int hw = pg & (HW - 1);
    int bi = pg >> 12;           // b*L + i
    int i  = bi & (Ln - 1);
    int b  = bi >> 4;
    int w  = hw & (Wn - 1);
    int h  = hw >> 6;

    // ix = u - 64*floor(u/64) - 0.5 with u = (w+0.5) + relx*32
    // iy = h + rely*32, clamped to [-1,64] (== reference masking w/ zero pad)
    const float uxb = (float)w + 0.5f;
    const float fyb = (float)h;

    const float* cumb = g_cum + (size_t)b * Ln * 2 * HW + hw;   // + (j*2+d)*HW
    const float cix = cumb[(size_t)(i * 2 + 0) * HW];
    const float ciy = cumb[(size_t)(i * 2 + 1) * HW];

    const float* imgb = g_imgT + (size_t)b * Ln * PLANE * Cn + cg * 4;

    float acc0 = 0.0f, acc1 = 0.0f, acc2 = 0.0f, acc3 = 0.0f;

#pragma unroll 4
    for (int j = 0; j <= i; j++) {
        float relx = cix - cumb[(size_t)(j * 2 + 0) * HW];
        float rely = ciy - cumb[(size_t)(j * 2 + 1) * HW];

        float u  = fmaf(relx, 32.0f, uxb);
        float fq = floorf(u * 0.015625f);           // u/64
        float ix = fmaf(fq, -64.0f, u) - 0.5f;      // in [-0.5, 63.5)
        float iy = fmaf(rely, 32.0f, fyb);
        iy = fminf(fmaxf(iy, -1.0f), 64.0f);

        float x0f = floorf(ix), y0f = floorf(iy);
        float wx = ix - x0f,    wy = iy - y0f;
        int x0 = (int)x0f, y0 = (int)y0f;           // x0 in [-1,63], y0 in [-1,64]

        float wx1 = 1.0f - wx, wy1 = 1.0f - wy;
        float w00 = wx1 * wy1, w01 = wx * wy1, w10 = wx1 * wy, w11 = wx * wy;

        int e = j * PLANE + y0 * PC + x0 + (PC + 1);   // always in-bounds
        const float* p = imgb + ((size_t)e << 4);

        const float4 v00 = *reinterpret_cast<const float4*>(p);
        const float4 v01 = *reinterpret_cast<const float4*>(p + Cn);
        const float4 v10 = *reinterpret_cast<const float4*>(p + PC * Cn);
        const float4 v11 = *reinterpret_cast<const float4*>(p + (PC + 1) * Cn);

        acc0 += w00 * v00.x + w01 * v01.x + w10 * v10.x + w11 * v11.x;
        acc1 += w00 * v00.y + w01 * v01.y + w10 * v10.y + w11 * v11.y;
        acc2 += w00 * v00.z + w01 * v01.z + w10 * v10.z + w11 * v11.z;
        acc3 += w00 * v00.w + w01 * v01.w + w10 * v10.w + w11 * v11.w;
    }

    // out[b,i,c,h,w]: this lane owns channels 4*cg .. 4*cg+3
    float* op = out + (size_t)bi * Cn * HW + (size_t)(cg * 4) * HW + hw;
    op[0 * HW] = acc0;
    op[1 * HW] = acc1;
    op[2 * HW] = acc2;
    op[3 * HW] = acc3;
}

extern "C" void kernel_launch(void* const* d_in, const int* in_sizes, int n_in,
                              void* d_out, int out_size) {
    const float* flows  = (const float*)d_in[0];   // (B,L,2,H,W)
    const float* images = (const float*)d_in[1];   // (B,L,C,H,W)
    float* out = (float*)d_out;                    // (B,L,C,H,W)

    const int nP = N_TRANS + N_CUM;        // 147456 prep threads
    prep_kernel<<<(nP + 255) / 256, 256>>>(images, flows);

    const int nM = Bn * Ln * HW * 4;       // 524288 main threads
    gridsample_pscan_kernel<<<(nM + 255) / 256, 256>>>(out);
}

// round 11
// speedup vs baseline: 1.9000x; 1.9000x over previous
#include <cuda_runtime.h>
#include <cuda_fp16.h>

// Problem constants
#define Bn 2
#define Ln 16
#define Cn 16
#define Hn 64
#define Wn 64
#define HW (Hn * Wn)            // 4096

// Padded transposed image, fp16: entry = 16 channels (32B).
// Rows cover y = -1..65 (PR=67), cols cover x = -1..64 (PC=66).
// Border entries are never written -> stay zero (device globals zero-init).
#define PR 67
#define PC 66
#define PLANE (PR * PC)         // 4422 entries per (b,l)

__device__ __half g_imgTh[Bn * Ln * PLANE * Cn];   // ~4.5 MB

static __device__ __forceinline__ unsigned pack_h2(float a, float b) {
    __half2 h = __floats2half2_rn(a, b);
    return *reinterpret_cast<unsigned*>(&h);
}

static __device__ __forceinline__ float4 ld_half4(const __half* p) {
    uint2 u = *reinterpret_cast<const uint2*>(p);
    __half2 h0 = *reinterpret_cast<const __half2*>(&u.x);
    __half2 h1 = *reinterpret_cast<const __half2*>(&u.y);
    float2 f0 = __half22float2(h0);
    float2 f1 = __half22float2(h1);
    return make_float4(f0.x, f0.y, f1.x, f1.y);
}

// ---------------------------------------------------------------------------
// Kernel 1: transpose images (B,L,C,H,W) -> padded fp16 (B,L,y,x,C).
// One thread per pixel: 16 coalesced float loads, 2 uint4 stores (32B).
// ---------------------------------------------------------------------------
__global__ void __launch_bounds__(256) transpose_kernel(const float* __restrict__ images) {
    int t = blockIdx.x * blockDim.x + threadIdx.x;   // 0 .. B*L*HW-1
    if (t >= Bn * Ln * HW) return;
    int hw = t & (HW - 1);
    int bl = t >> 12;
    int w = hw & (Wn - 1);
    int h = hw >> 6;

    const float* src = images + (size_t)bl * Cn * HW + hw;
    float v[Cn];
#pragma unroll
    for (int c = 0; c < Cn; c++) v[c] = src[(size_t)c * HW];

    size_t e = (size_t)bl * PLANE + (size_t)(h + 1) * PC + (w + 1);
    uint4* dst = reinterpret_cast<uint4*>(g_imgTh + e * Cn);
    dst[0] = make_uint4(pack_h2(v[0], v[1]),  pack_h2(v[2], v[3]),
                        pack_h2(v[4], v[5]),  pack_h2(v[6], v[7]));
    dst[1] = make_uint4(pack_h2(v[8], v[9]),  pack_h2(v[10], v[11]),
                        pack_h2(v[12], v[13]), pack_h2(v[14], v[15]));
}

// ---------------------------------------------------------------------------
// Kernel 2: main (round-5 structure, verbatim: serial flow accumulation keeps
// per-warp MLP low -> shallow L1tex queue, no cross-CTA spread blowup).
// 4 lanes per pixel, each lane owns 4 channels (8B fp16 per corner).
// A warp's corner gather spans 256B contiguous (2-3 L1 wavefronts).
// ---------------------------------------------------------------------------
__global__ void __launch_bounds__(256) gridsample_pscan_kernel(const float* __restrict__ flows,
                                                               float* __restrict__ out) {
    int t = blockIdx.x * blockDim.x + threadIdx.x;   // 0 .. B*L*HW*4-1
    if (t >= Bn * Ln * HW * 4) return;
    int cg = t & 3;              // channel group (4 channels)
    int pg = t >> 2;             // b*L*HW + hw
    int hw = pg & (HW - 1);
    int bi = pg >> 12;           // b*L + i
    int i  = bi & (Ln - 1);
    int b  = bi >> 4;
    int w  = hw & (Wn - 1);
    int h  = hw >> 6;

    const float uxb = (float)w + 0.5f;
    const float fyb = (float)h;

    const float* flowb = flows + (size_t)b * Ln * 2 * HW + hw;     // + (j*2+d)*HW
    const __half* imgb = g_imgTh + (size_t)b * Ln * PLANE * Cn + cg * 4;

    float relx = 0.0f, rely = 0.0f;   // cum_i - cum_j ; zero at j = i
    float acc0 = 0.0f, acc1 = 0.0f, acc2 = 0.0f, acc3 = 0.0f;

#pragma unroll 2
    for (int j = i; j >= 0; --j) {
        // x: wrap into [0,64), then shift by -0.5
        float u  = fmaf(relx, 32.0f, uxb);
        float fq = floorf(u * 0.015625f);           // u/64
        float ix = fmaf(fq, -64.0f, u) - 0.5f;      // in [-0.5, 63.5)
        // y: clamp to [-1, 64] (equivalent to validity masking w/ zero border)
        float iy = fmaf(rely, 32.0f, fyb);
        iy = fminf(fmaxf(iy, -1.0f), 64.0f);

        float x0f = floorf(ix), y0f = floorf(iy);
        float wx = ix - x0f,    wy = iy - y0f;
        int x0 = (int)x0f, y0 = (int)y0f;           // x0 in [-1,63], y0 in [-1,64]

        float wx1 = 1.0f - wx, wy1 = 1.0f - wy;
        float w00 = wx1 * wy1, w01 = wx * wy1, w10 = wx1 * wy, w11 = wx * wy;

        // entry index: j*PLANE + (y0+1)*PC + (x0+1) -> always in-bounds
        int e = j * PLANE + y0 * PC + x0 + (PC + 1);
        const __half* p = imgb + ((size_t)e << 4);   // e * 16 halves

        const float4 v00 = ld_half4(p);
        const float4 v01 = ld_half4(p + Cn);
        const float4 v10 = ld_half4(p + PC * Cn);
        const float4 v11 = ld_half4(p + (PC + 1) * Cn);

        acc0 += w00 * v00.x + w01 * v01.x + w10 * v10.x + w11 * v11.x;
        acc1 += w00 * v00.y + w01 * v01.y + w10 * v10.y + w11 * v11.y;
        acc2 += w00 * v00.z + w01 * v01.z + w10 * v10.z + w11 * v11.z;
        acc3 += w00 * v00.w + w01 * v01.w + w10 * v10.w + w11 * v11.w;

        // advance rel to (i, j-1): rel += flow[j]
        relx += flowb[(size_t)(j * 2 + 0) * HW];
        rely += flowb[(size_t)(j * 2 + 1) * HW];
    }

    // out[b,i,c,h,w]: this lane owns channels 4*cg .. 4*cg+3
    float* op = out + (size_t)bi * Cn * HW + (size_t)(cg * 4) * HW + hw;
    op[0 * HW] = acc0;
    op[1 * HW] = acc1;
    op[2 * HW] = acc2;
    op[3 * HW] = acc3;
}

extern "C" void kernel_launch(void* const* d_in, const int* in_sizes, int n_in,
                              void* d_out, int out_size) {
    const float* flows  = (const float*)d_in[0];   // (B,L,2,H,W)
    const float* images = (const float*)d_in[1];   // (B,L,C,H,W)
    float* out = (float*)d_out;                    // (B,L,C,H,W)

    const int nT = Bn * Ln * HW;           // 131072 transpose threads
    transpose_kernel<<<(nT + 255) / 256, 256>>>(images);

    const int nM = Bn * Ln * HW * 4;       // 524288 main threads
    gridsample_pscan_kernel<<<(nM + 255) / 256, 256>>>(flows, out);
}